// round 12
// baseline (speedup 1.0000x reference)
#include <cuda_runtime.h>

// PeptidePocketConvLayer — GB300 sm_103a
//
// Inputs: d_in[0] peptide f32 [B,15,20], d_in[1] pocket i32 [B,34],
//         d_in[2] kernel f32 [20,9].  Output f32 [B,34,28].
//
//  - pocket mask periodic 9 -> agg[q] = pep[q] + (jb!=q ? pep[jb] : 0), jb=3*(q%3)
//  - peptide rows 9..14 never referenced
//  - zero-padded agg rows (logical -8..27), conv is branch-free aligned LDS.128
//  - G=8 batches/block; conv thread = one (g,pocket) FULL 28-wide row:
//    agg row read once (9 LDS.128, rolling window) and lanes of a warp share
//    only 9 distinct agg rows -> crossbar dedup (round-10 lesson: wavefront
//    bytes, not LDS instruction count, is the binder)

#define NPOCK   34
#define OUT_F4  238          // 34*28/4 float4 per batch
#define PEP_F4  75           // 15*20/4 float4 per batch (global)
#define AGG_W   36           // padded agg row words: logical -8..27
#define FSTR    12           // padded filter row words (48B)
#define G       8            // batches per block
#define NTHR    288          // 9 warps; 272 conv tasks in one pass

__global__ __launch_bounds__(NTHR, 6)
void pep_pocket_conv_kernel(const float* __restrict__ pep,
                            const int*   __restrict__ pock,
                            const float* __restrict__ ker,
                            float*       __restrict__ out)
{
    __shared__ __align__(16) float4 sPepV[G * 45];           // rows 0..8 x 20 /batch
    __shared__ __align__(16) float  sAgg[G * 9 * AGG_W];     // padded agg rows
    __shared__ __align__(16) float  sFilt[G * NPOCK * FSTR]; // padded filter rows
    __shared__ int sId[G * NPOCK];

    const int b0 = blockIdx.x * G;
    const int t  = threadIdx.x;

    // ---- stage: pocket ids (272) + peptide rows 0..8 (360 f4) ----
    if (t < G * NPOCK) {
        int g = t / NPOCK, r = t - g * NPOCK;
        sId[t] = pock[(size_t)(b0 + g) * NPOCK + r];
    }
    for (int i = t; i < G * 45; i += NTHR) {
        int g = i / 45, r = i - g * 45;
        sPepV[i] = __ldg((const float4*)pep + (size_t)(b0 + g) * PEP_F4 + r);
    }
    __syncthreads();

    // ---- gather filters into padded rows: sFilt[(g*34+p)*12 + j] ----
    for (int i = t; i < G * NPOCK * 9; i += NTHR) {
        int pp = i / 9, j = i - pp * 9;          // pp = g*34 + p
        sFilt[pp * FSTR + j] = __ldg(ker + sId[pp] * 9 + j);
    }

    // ---- aggregates, float4-wide; every slot written exactly once ----
    // per batch: 9 rows x 9 f4-slots (slots 0,1,7,8 zero pad; 2..6 data)
    for (int s = t; s < G * 81; s += NTHR) {
        int g = s / 81, r = s - g * 81;
        int q = r / 9,  a = r - q * 9;
        float4 v = make_float4(0.f, 0.f, 0.f, 0.f);
        if (a >= 2 && a <= 6) {
            int c  = a - 2;
            int jb = 3 * (q - 3 * (q / 3));      // 3*(q%3)
            float4 u = sPepV[g * 45 + q * 5 + c];
            if (jb != q) {
                float4 w = sPepV[g * 45 + jb * 5 + c];
                u.x += w.x; u.y += w.y; u.z += w.z; u.w += w.w;
            }
            v = u;
        }
        ((float4*)sAgg)[s] = v;                  // s == g*81 + q*9 + a
    }
    __syncthreads();

    // ---- conv: thread = (g, pocket), full 28-wide row, single pass ----
    if (t < G * NPOCK) {
        const int g = t / NPOCK;
        const int p = t - g * NPOCK;
        const int q = p - 9 * (p / 9);           // p % 9

        // filter row (task-indexed layout matches gather: pp == t)
        const float* fB = &sFilt[t * FSTR];
        float4 f03 = *(const float4*)(fB + 0);
        float4 f47 = *(const float4*)(fB + 4);
        float  f8v = fB[8];
        float f[9] = { f03.x, f03.y, f03.z, f03.w,
                       f47.x, f47.y, f47.z, f47.w, f8v };

        // agg row: lanes of a warp share (mostly) one g -> 9 distinct rows,
        // crossbar dedups the LDS.128s.
        const float* rowp = &sAgg[(g * 9 + q) * AGG_W];
        float4* outV = (float4*)out + (size_t)(b0 + g) * OUT_F4 + p * 7;

        // rolling 12-word window, logical indices start at -8
        float w[12];
        {
            float4 w0 = *(const float4*)(rowp + 0);
            float4 w1 = *(const float4*)(rowp + 4);
            float4 w2 = *(const float4*)(rowp + 8);
            w[0]=w0.x; w[1]=w0.y; w[2]=w0.z; w[3]=w0.w;
            w[4]=w1.x; w[5]=w1.y; w[6]=w1.z; w[7]=w1.w;
            w[8]=w2.x; w[9]=w2.y; w[10]=w2.z; w[11]=w2.w;
        }

        #pragma unroll
        for (int c = 0; c < 7; ++c) {
            // window holds logical 4c-8 .. 4c+3; out[4c+d] = sum_j f[j]*agg[4c+d-j]
            float o0 = 0.f, o1 = 0.f, o2 = 0.f, o3 = 0.f;
            #pragma unroll
            for (int j = 0; j < 9; ++j) {
                o0 = fmaf(f[j], w[8  - j], o0);
                o1 = fmaf(f[j], w[9  - j], o1);
                o2 = fmaf(f[j], w[10 - j], o2);
                o3 = fmaf(f[j], w[11 - j], o3);
            }
            __stcs(&outV[c], make_float4(o0, o1, o2, o3));

            if (c < 6) {                          // slide window by 4
                #pragma unroll
                for (int i = 0; i < 8; ++i) w[i] = w[i + 4];
                float4 nw = *(const float4*)(rowp + (c + 3) * 4);
                w[8]=nw.x; w[9]=nw.y; w[10]=nw.z; w[11]=nw.w;
            }
        }
    }
}

extern "C" void kernel_launch(void* const* d_in, const int* in_sizes, int n_in,
                              void* d_out, int out_size)
{
    const float* pep  = (const float*)d_in[0];
    const int*   pock = (const int*)d_in[1];
    const float* ker  = (const float*)d_in[2];
    float*       out  = (float*)d_out;

    const int B = in_sizes[1] / NPOCK;   // pocket_encoding is [B, 34]

    pep_pocket_conv_kernel<<<B / G, NTHR>>>(pep, pock, ker, out);
}

// round 13
// speedup vs baseline: 1.6798x; 1.6798x over previous
#include <cuda_runtime.h>

// PeptidePocketConvLayer — GB300 sm_103a
//
// Inputs: d_in[0] peptide f32 [B,15,20], d_in[1] pocket i32 [B,34],
//         d_in[2] kernel f32 [20,9].  Output f32 [B,34,28].
//
//  - pocket mask periodic 9 -> agg[q] = pep[q] + (jb!=q ? pep[jb] : 0), jb=3*(q%3)
//  - peptide rows 9..14 never referenced
//  - zero-padded agg rows (logical -8..27): conv is branch-free aligned LDS.128
//  - G=8 batches/block, 9 warps; conv warp w -> q=w, lane=(i,c): p=q+9*i, k0=4c
//      * agg addresses independent of i  -> 7 distinct f4/warp -> ~1 wf per LDS.128
//      * filter addresses independent of c -> 4 distinct f4/warp -> ~1 wf
//      * stores: per i-group 7 consecutive f4 (112B runs) -> coalesced
//    (round-12 lesson: never stride stores within one STG; dedup via mapping)

#define NPOCK   34
#define OUT_F4  238          // 34*28/4 float4 per batch
#define PEP_F4  75           // 15*20/4 float4 per batch (global)
#define AGG_W   36           // padded agg row words: logical -8..27
#define FSTR    12           // padded filter row words (48B)
#define G       8            // batches per block
#define NTHR    288          // 9 warps

__global__ __launch_bounds__(NTHR, 7)
void pep_pocket_conv_kernel(const float* __restrict__ pep,
                            const int*   __restrict__ pock,
                            const float* __restrict__ ker,
                            float*       __restrict__ out)
{
    __shared__ __align__(16) float4 sPepV[G * 45];           // rows 0..8 x 20 /batch
    __shared__ __align__(16) float  sAgg[G * 9 * AGG_W];     // padded agg rows
    __shared__ __align__(16) float  sFilt[G * NPOCK * FSTR]; // padded filter rows
    __shared__ int sId[G * NPOCK];

    const int b0 = blockIdx.x * G;
    const int t  = threadIdx.x;

    // ---- stage: pocket ids (272) + peptide rows 0..8 (360 f4) ----
    if (t < G * NPOCK) {
        int g = t / NPOCK, r = t - g * NPOCK;
        sId[t] = pock[(size_t)(b0 + g) * NPOCK + r];
    }
    for (int i = t; i < G * 45; i += NTHR) {
        int g = i / 45, r = i - g * 45;
        sPepV[i] = __ldg((const float4*)pep + (size_t)(b0 + g) * PEP_F4 + r);
    }
    __syncthreads();

    // ---- gather filters into padded rows: sFilt[(g*34+p)*12 + j] ----
    for (int i = t; i < G * NPOCK * 9; i += NTHR) {
        int pp = i / 9, j = i - pp * 9;          // pp = g*34 + p
        sFilt[pp * FSTR + j] = __ldg(ker + sId[pp] * 9 + j);
    }

    // ---- aggregates, float4-wide; every slot written exactly once ----
    // per batch: 9 rows x 9 f4-slots (slots 0,1,7,8 zero pad; 2..6 data)
    for (int s = t; s < G * 81; s += NTHR) {
        int g = s / 81, r = s - g * 81;
        int q = r / 9,  a = r - q * 9;
        float4 v = make_float4(0.f, 0.f, 0.f, 0.f);
        if (a >= 2 && a <= 6) {
            int c  = a - 2;
            int jb = 3 * (q - 3 * (q / 3));      // 3*(q%3)
            float4 u = sPepV[g * 45 + q * 5 + c];
            if (jb != q) {
                float4 w = sPepV[g * 45 + jb * 5 + c];
                u.x += w.x; u.y += w.y; u.z += w.z; u.w += w.w;
            }
            v = u;
        }
        ((float4*)sAgg)[s] = v;                  // s == g*81 + q*9 + a
    }
    __syncthreads();

    // ---- conv: warp w -> q=w; lane=(i,c): pocket p=q+9i, output f4 k0=4c ----
    {
        const int wrp  = t >> 5;                 // 0..8 == q
        const int lane = t & 31;
        const int i    = lane / 7;               // 0..4 (4 inactive except i<np)
        const int c    = lane - i * 7;           // 0..6
        const int q    = wrp;
        const int p    = q + 9 * i;
        const int np   = (q < 7) ? 4 : 3;        // pockets with this q (34 = 9*3+7)

        if (i < np) {
            const float* fB   = &sFilt[p * FSTR];            // +34*FSTR per g
            const float* rowp = &sAgg[q * AGG_W + 4 * c];    // +9*AGG_W per g
            float4* outV = (float4*)out + (size_t)b0 * OUT_F4 + p * 7 + c;

            #pragma unroll
            for (int g = 0; g < G; ++g) {
                // filter row: addresses depend only on i -> 4 distinct -> 1 wf
                float4 f03 = *(const float4*)(fB + 0);
                float4 f47 = *(const float4*)(fB + 4);
                float  f8v = fB[8];
                float f[9] = { f03.x, f03.y, f03.z, f03.w,
                               f47.x, f47.y, f47.z, f47.w, f8v };

                // agg window: logical k0-8..k0+3; addresses depend only on c
                float4 a0 = *(const float4*)(rowp + 0);
                float4 a1 = *(const float4*)(rowp + 4);
                float4 a2 = *(const float4*)(rowp + 8);
                float a[12] = { a0.x, a0.y, a0.z, a0.w,
                                a1.x, a1.y, a1.z, a1.w,
                                a2.x, a2.y, a2.z, a2.w };

                float o0 = 0.f, o1 = 0.f, o2 = 0.f, o3 = 0.f;
                #pragma unroll
                for (int j = 0; j < 9; ++j) {    // out[k] = sum_j f[j]*agg[k-j]
                    o0 = fmaf(f[j], a[8  - j], o0);
                    o1 = fmaf(f[j], a[9  - j], o1);
                    o2 = fmaf(f[j], a[10 - j], o2);
                    o3 = fmaf(f[j], a[11 - j], o3);
                }

                __stcs(&outV[g * OUT_F4], make_float4(o0, o1, o2, o3));

                fB   += NPOCK * FSTR;
                rowp += 9 * AGG_W;
            }
        }
    }
}

extern "C" void kernel_launch(void* const* d_in, const int* in_sizes, int n_in,
                              void* d_out, int out_size)
{
    const float* pep  = (const float*)d_in[0];
    const int*   pock = (const int*)d_in[1];
    const float* ker  = (const float*)d_in[2];
    float*       out  = (float*)d_out;

    const int B = in_sizes[1] / NPOCK;   // pocket_encoding is [B, 34]

    pep_pocket_conv_kernel<<<B / G, NTHR>>>(pep, pock, ker, out);
}

// round 14
// speedup vs baseline: 2.1722x; 1.2931x over previous
#include <cuda_runtime.h>

// PeptidePocketConvLayer — GB300 sm_103a
//
// Inputs: d_in[0] peptide f32 [B,15,20], d_in[1] pocket i32 [B,34],
//         d_in[2] kernel f32 [20,9].  Output f32 [B,34,28].
//
//  - pocket mask periodic 9 -> agg[q] = pep[q] + (jb!=q ? pep[jb] : 0), jb=3*(q%3)
//  - peptide rows 9..14 never referenced
//  - zero-padded agg rows (logical -8..27): conv is branch-free aligned LDS.128
//  - G=8 batches/block, 9 warps; conv warp w -> q=w, lane=(i,c): p=q+9i, k0=4c
//      * agg addresses depend only on c -> 7 distinct f4/warp -> ~1 wf per LDS.128
//      * filter addresses depend only on i -> 4 distinct f4/warp -> ~1 wf,
//        so the raw kernel table can be id-indexed DIRECTLY (no gather phase)
//      * stores: per i-group 7 consecutive f4 (112B runs) -> coalesced
//  - peptide staged with cp.async.cg (global->smem direct; no STS pass)

#define NPOCK   34
#define OUT_F4  238          // 34*28/4 float4 per batch
#define PEP_F4  75           // 15*20/4 float4 per batch (global)
#define AGG_W   36           // padded agg row words: logical -8..27
#define FSTR    12           // padded kernel row words (48B, 16B-aligned)
#define G       8            // batches per block
#define NTHR    288          // 9 warps

__global__ __launch_bounds__(NTHR, 7)
void pep_pocket_conv_kernel(const float* __restrict__ pep,
                            const int*   __restrict__ pock,
                            const float* __restrict__ ker,
                            float*       __restrict__ out)
{
    __shared__ __align__(16) float4 sPepV[G * 45];        // rows 0..8 x 20 /batch
    __shared__ __align__(16) float  sAgg[G * 9 * AGG_W];  // padded agg rows
    __shared__ __align__(16) float  sKer[20 * FSTR];      // raw kernel, padded rows
    __shared__ int sId[G * NPOCK];

    const int b0 = blockIdx.x * G;
    const int t  = threadIdx.x;

    // ---- stage peptide rows 0..8 via cp.async (360 x 16B, no STS pass) ----
    for (int i = t; i < G * 45; i += NTHR) {
        int g = i / 45, r = i - g * 45;
        const float4* src = (const float4*)pep + (size_t)(b0 + g) * PEP_F4 + r;
        unsigned sdst = (unsigned)__cvta_generic_to_shared(&sPepV[i]);
        asm volatile("cp.async.cg.shared.global [%0], [%1], 16;\n"
                     :: "r"(sdst), "l"(src));
    }
    // ---- pocket ids + raw kernel table (tiny, plain LDG/STS) ----
    if (t < G * NPOCK) {
        int g = t / NPOCK, r = t - g * NPOCK;
        sId[t] = pock[(size_t)(b0 + g) * NPOCK + r];
    }
    if (t < 180) {
        int r = t / 9, j = t - r * 9;
        sKer[r * FSTR + j] = __ldg(ker + t);
    }
    asm volatile("cp.async.commit_group;\ncp.async.wait_group 0;\n" ::: "memory");
    __syncthreads();

    // ---- aggregates, float4-wide; every slot written exactly once ----
    // per batch: 9 rows x 9 f4-slots (slots 0,1,7,8 zero pad; 2..6 data)
    for (int s = t; s < G * 81; s += NTHR) {
        int g = s / 81, r = s - g * 81;
        int q = r / 9,  a = r - q * 9;
        float4 v = make_float4(0.f, 0.f, 0.f, 0.f);
        if (a >= 2 && a <= 6) {
            int c  = a - 2;
            int jb = 3 * (q - 3 * (q / 3));      // 3*(q%3)
            float4 u = sPepV[g * 45 + q * 5 + c];
            if (jb != q) {
                float4 w = sPepV[g * 45 + jb * 5 + c];
                u.x += w.x; u.y += w.y; u.z += w.z; u.w += w.w;
            }
            v = u;
        }
        ((float4*)sAgg)[s] = v;                  // s == g*81 + q*9 + a
    }
    __syncthreads();

    // ---- conv: warp w -> q=w; lane=(i,c): pocket p=q+9i, output f4 k0=4c ----
    {
        const int lane = t & 31;
        const int q    = t >> 5;                 // 0..8
        const int i    = lane / 7;               // 0..4 (i==4 inactive)
        const int c    = lane - i * 7;           // 0..6
        const int p    = q + 9 * i;
        const int np   = (q < 7) ? 4 : 3;        // pockets with this q (34=9*3+7)

        if (i < np) {
            // hoist the 8 per-batch pocket ids (broadcast scalar LDS)
            int ids[G];
            #pragma unroll
            for (int g = 0; g < G; ++g) ids[g] = sId[g * NPOCK + p];

            const float* rowp = &sAgg[q * AGG_W + 4 * c];    // +9*AGG_W per g
            float4* outV = (float4*)out + (size_t)b0 * OUT_F4 + p * 7 + c;

            #pragma unroll
            for (int g = 0; g < G; ++g) {
                // filter row by amino-acid id: 4 distinct addresses/warp -> dedup
                const float* fr = &sKer[ids[g] * FSTR];
                float4 f03 = *(const float4*)(fr + 0);
                float4 f47 = *(const float4*)(fr + 4);
                float  f8v = fr[8];
                float f[9] = { f03.x, f03.y, f03.z, f03.w,
                               f47.x, f47.y, f47.z, f47.w, f8v };

                // agg window: logical 4c-8..4c+3; addresses depend only on c
                float4 a0 = *(const float4*)(rowp + 0);
                float4 a1 = *(const float4*)(rowp + 4);
                float4 a2 = *(const float4*)(rowp + 8);
                float a[12] = { a0.x, a0.y, a0.z, a0.w,
                                a1.x, a1.y, a1.z, a1.w,
                                a2.x, a2.y, a2.z, a2.w };

                float o0 = 0.f, o1 = 0.f, o2 = 0.f, o3 = 0.f;
                #pragma unroll
                for (int j = 0; j < 9; ++j) {    // out[k] = sum_j f[j]*agg[k-j]
                    o0 = fmaf(f[j], a[8  - j], o0);
                    o1 = fmaf(f[j], a[9  - j], o1);
                    o2 = fmaf(f[j], a[10 - j], o2);
                    o3 = fmaf(f[j], a[11 - j], o3);
                }

                __stcs(&outV[g * OUT_F4], make_float4(o0, o1, o2, o3));

                rowp += 9 * AGG_W;
            }
        }
    }
}

extern "C" void kernel_launch(void* const* d_in, const int* in_sizes, int n_in,
                              void* d_out, int out_size)
{
    const float* pep  = (const float*)d_in[0];
    const int*   pock = (const int*)d_in[1];
    const float* ker  = (const float*)d_in[2];
    float*       out  = (float*)d_out;

    const int B = in_sizes[1] / NPOCK;   // pocket_encoding is [B, 34]

    pep_pocket_conv_kernel<<<B / G, NTHR>>>(pep, pock, ker, out);
}